// round 1
// baseline (speedup 1.0000x reference)
#include <cuda_runtime.h>

#define NN   50000
#define DEG  16
#define DIM  128
#define EDIM 32
#define HDIM 256   // 2*DIM
#define NPB  8     // nodes per block in edge kernel

// ---- scratch (device globals; no allocation allowed) ----
__device__ float g_P[NN * 512];    // [N, 512]: cols 0..255 = P_s = x@We1[0:128], 256..511 = P_r = x@We1[128:256]
__device__ float g_S[NN * HDIM];   // [N, 256]: sum over 16 edges of swish(h_pre)
__device__ float g_AGG[NN * DIM];  // [N, 128]: LN'd aggregated messages
__device__ float g_U[NN * HDIM];   // [N, 256]: swish hidden of node MLP

__device__ __forceinline__ float swishf(float v) {
    return v / (1.0f + __expf(-v));
}

// ============================================================================
// Fused tiled GEMM: C[M, NC] = A[M, K] @ B[K, NC] (+ epilogue per MODE)
//   MODE 0: plain store (for P; out has ldOut/outOff)
//   MODE 1: val = acc*scale + bias[c];                  LN(gamma,beta)*mask -> out
//   MODE 2: val = swish(acc + bias[c]) -> out           (A = concat(A0, A1) along K)
//   MODE 3: val = acc + bias[c] + resid[row*NC + c];    LN(gamma,beta)*mask -> out
// blockDim.x == NC (128 or 256). Each thread owns one output column for BM rows.
// A tile staged transposed in smem; inner loop reads A via broadcast LDS.128.
// ============================================================================
template<int K, int NC, int MODE>
__global__ void __launch_bounds__(NC) gemm_fused(
    const float* __restrict__ A0, const float* __restrict__ A1,
    const float* __restrict__ B, int ldB,
    const float* __restrict__ bias, float scale,
    const float* __restrict__ gamma, const float* __restrict__ beta,
    const float* __restrict__ mask, const float* __restrict__ resid,
    float* __restrict__ out, int ldOut, int outOff)
{
    constexpr int BM = 32;
    constexpr int BK = 16;
    constexpr bool LN = (MODE == 1 || MODE == 3);

    __shared__ __align__(16) float Asm[BK][BM + 4];       // transposed A tile, padded
    __shared__ float tl[LN ? BM * 132 : 1];               // row-major tile for LN reduce
    __shared__ float sm_mean[BM], sm_rstd[BM];

    const int n0 = blockIdx.x * BM;
    const int c  = threadIdx.x;

    float acc[BM];
    #pragma unroll
    for (int r = 0; r < BM; r++) acc[r] = 0.0f;

    for (int kb = 0; kb < K; kb += BK) {
        // preload B column segment into registers (L1/L2 resident weights)
        float bv[BK];
        #pragma unroll
        for (int kk = 0; kk < BK; kk++) bv[kk] = B[(kb + kk) * ldB + c];

        // stage A tile (transposed)
        constexpr int LPT = (BM * BK) / NC;
        #pragma unroll
        for (int i = 0; i < LPT; i++) {
            int idx = c + i * NC;
            int r = idx / BK, k = idx % BK;
            int row = n0 + r;
            int gk = kb + k;
            float a = 0.0f;
            if (row < NN) {
                if (MODE == 2)
                    a = (gk < DIM) ? A0[row * DIM + gk] : A1[row * DIM + (gk - DIM)];
                else
                    a = A0[row * K + gk];
            }
            Asm[k][r] = a;
        }
        __syncthreads();

        #pragma unroll
        for (int kk = 0; kk < BK; kk++) {
            float b = bv[kk];
            const float4* ap = reinterpret_cast<const float4*>(&Asm[kk][0]);
            #pragma unroll
            for (int j = 0; j < BM / 4; j++) {
                float4 a = ap[j];
                acc[4*j+0] += a.x * b;
                acc[4*j+1] += a.y * b;
                acc[4*j+2] += a.z * b;
                acc[4*j+3] += a.w * b;
            }
        }
        __syncthreads();
    }

    // ------------------ epilogue ------------------
    if (MODE == 0) {
        #pragma unroll
        for (int r = 0; r < BM; r++) {
            int row = n0 + r;
            if (row < NN) out[row * ldOut + outOff + c] = acc[r];
        }
        return;
    }
    if (MODE == 2) {
        float be = bias[c];
        #pragma unroll
        for (int r = 0; r < BM; r++) {
            int row = n0 + r;
            if (row < NN) out[row * ldOut + c] = swishf(acc[r] + be);
        }
        return;
    }
    if (LN) {
        float be = bias[c];
        float val[BM];
        #pragma unroll
        for (int r = 0; r < BM; r++) {
            int row = n0 + r;
            float v = acc[r] * scale + be;
            if (MODE == 3 && row < NN) v += resid[row * NC + c];
            val[r] = v;
            tl[r * 132 + c] = v;
        }
        __syncthreads();

        const int warp = c >> 5, lane = c & 31;
        #pragma unroll
        for (int i = 0; i < 8; i++) {
            int r = warp + 4 * i;
            float s = 0.0f, s2 = 0.0f;
            #pragma unroll
            for (int j = 0; j < 4; j++) {
                float x = tl[r * 132 + lane + 32 * j];
                s += x; s2 += x * x;
            }
            #pragma unroll
            for (int o = 16; o > 0; o >>= 1) {
                s  += __shfl_xor_sync(0xffffffffu, s,  o);
                s2 += __shfl_xor_sync(0xffffffffu, s2, o);
            }
            if (lane == 0) {
                float m = s * (1.0f / 128.0f);
                float var = s2 * (1.0f / 128.0f) - m * m;
                sm_mean[r] = m;
                sm_rstd[r] = rsqrtf(var + 1e-5f);
            }
        }
        __syncthreads();

        float gc = gamma[c], bc = beta[c];
        #pragma unroll
        for (int r = 0; r < BM; r++) {
            int row = n0 + r;
            if (row < NN) {
                float mk = mask[row];
                out[row * ldOut + c] =
                    ((val[r] - sm_mean[r]) * sm_rstd[r] * gc + bc) * mk;
            }
        }
    }
}

// ============================================================================
// Edge kernel: per node n (16 contiguous edges, receivers == repeat(arange,16)):
//   h_e = swish(P_s[senders[e]] + P_r[n] + ef[e] @ We1[256:288] + be1)
//   S[n] = sum_e h_e
// Block = 256 threads (one per output channel), NPB nodes per block.
// ============================================================================
__global__ void __launch_bounds__(256) edge_kernel(
    const float* __restrict__ edge_feat, const int* __restrict__ senders,
    const float* __restrict__ We1, const float* __restrict__ be1)
{
    __shared__ __align__(16) float ef[NPB * DEG * EDIM];  // 16 KB
    __shared__ int snd[NPB * DEG];

    const int t  = threadIdx.x;
    const int n0 = blockIdx.x * NPB;
    const int cnt = min(NPB, NN - n0);
    const int e0 = n0 * DEG;

    const int totf = cnt * DEG * EDIM;
    for (int j = t; j < totf; j += 256) ef[j] = edge_feat[e0 * EDIM + j];
    for (int j = t; j < cnt * DEG; j += 256) snd[j] = senders[e0 + j];

    // edge-feature weight column t (rows 256..287 of We1) in registers
    float w[EDIM];
    #pragma unroll
    for (int k = 0; k < EDIM; k++) w[k] = We1[(256 + k) * 256 + t];
    const float b1 = be1[t];
    __syncthreads();

    for (int ni = 0; ni < cnt; ni++) {
        const int n = n0 + ni;
        const float pr = g_P[n * 512 + 256 + t] + b1;  // receiver projection + bias
        float sacc = 0.0f;
        #pragma unroll
        for (int e = 0; e < DEG; e++) {
            const int le = ni * DEG + e;
            const int s = snd[le];
            float v = pr + g_P[s * 512 + t];           // sender projection (L2 gather)
            const float4* efp = reinterpret_cast<const float4*>(&ef[le * EDIM]);
            #pragma unroll
            for (int q = 0; q < EDIM / 4; q++) {
                float4 f = efp[q];
                v += f.x * w[4*q] + f.y * w[4*q+1] + f.z * w[4*q+2] + f.w * w[4*q+3];
            }
            sacc += swishf(v);
        }
        g_S[n * HDIM + t] = sacc;
    }
}

// ============================================================================
extern "C" void kernel_launch(void* const* d_in, const int* in_sizes, int n_in,
                              void* d_out, int out_size)
{
    const float* node_inp  = (const float*)d_in[0];
    const float* edge_feat = (const float*)d_in[1];
    const float* node_mask = (const float*)d_in[2];
    const float* We1       = (const float*)d_in[3];
    const float* be1       = (const float*)d_in[4];
    const float* We2       = (const float*)d_in[5];
    const float* be2       = (const float*)d_in[6];
    const float* g_msg     = (const float*)d_in[7];
    const float* b_msg     = (const float*)d_in[8];
    const float* Wn1       = (const float*)d_in[9];
    const float* bn1       = (const float*)d_in[10];
    const float* Wn2       = (const float*)d_in[11];
    const float* bn2       = (const float*)d_in[12];
    const float* g_node    = (const float*)d_in[13];
    const float* b_node    = (const float*)d_in[14];
    const int*   senders   = (const int*)d_in[15];
    float* out = (float*)d_out;

    float *Pp, *Sp, *AGGp, *Up;
    cudaGetSymbolAddress((void**)&Pp,   g_P);
    cudaGetSymbolAddress((void**)&Sp,   g_S);
    cudaGetSymbolAddress((void**)&AGGp, g_AGG);
    cudaGetSymbolAddress((void**)&Up,   g_U);

    const dim3 gRows((NN + 31) / 32);

    // 1) per-node projections: P_s = x @ We1[0:128], P_r = x @ We1[128:256]
    gemm_fused<128, 256, 0><<<gRows, 256>>>(
        node_inp, nullptr, We1, 256,
        nullptr, 1.0f, nullptr, nullptr, nullptr, nullptr, Pp, 512, 0);
    gemm_fused<128, 256, 0><<<gRows, 256>>>(
        node_inp, nullptr, We1 + 128 * 256, 256,
        nullptr, 1.0f, nullptr, nullptr, nullptr, nullptr, Pp, 512, 256);

    // 2) per-edge swish + segment sum -> S[N,256]
    edge_kernel<<<(NN + NPB - 1) / NPB, 256>>>(edge_feat, senders, We1, be1);

    // 3) agg = LN(S @ We2 / 16 + be2; g_msg, b_msg) * mask
    gemm_fused<256, 128, 1><<<gRows, 128>>>(
        Sp, nullptr, We2, 128,
        be2, 1.0f / 16.0f, g_msg, b_msg, node_mask, nullptr, AGGp, 128, 0);

    // 4) U = swish([node_inp, agg] @ Wn1 + bn1)
    gemm_fused<256, 256, 2><<<gRows, 256>>>(
        node_inp, AGGp, Wn1, 256,
        bn1, 1.0f, nullptr, nullptr, nullptr, nullptr, Up, 256, 0);

    // 5) out = LN(node_inp + U @ Wn2 + bn2; g_node, b_node) * mask
    gemm_fused<256, 128, 3><<<gRows, 128>>>(
        Up, nullptr, Wn2, 128,
        bn2, 1.0f, g_node, b_node, node_mask, node_inp, out, 128, 0);
}